// round 4
// baseline (speedup 1.0000x reference)
#include <cuda_runtime.h>

#define T_STEPS 2000
#define BATCH   256
#define SEQ     10000
#define KW      5

// Gate pre-activations a_x[t][b][j] = LN64(xt@Wx^T)[j]*gx[j] + bx[j] + b_gates[j],
// stored so float2 at (t*256+b)*32 + l = { a[j=l], a[j=l+32] }.
__device__ float g_ax[(size_t)T_STEPS * BATCH * 64];
// Precomputed conv collapse (valid when b_mlp == 0): P/N[o*5+k]
__device__ float g_P[80];
__device__ float g_N[80];
__device__ int   g_bmnz;

__device__ __forceinline__ float sigf(float x) {
    return __fdividef(1.0f, 1.0f + __expf(-x));
}

// ---- f32x2 packed helpers (sm_103a) --------------------------------------
__device__ __forceinline__ unsigned long long pk2(float lo, float hi) {
    unsigned long long r;
    asm("mov.b64 %0, {%1, %2};" : "=l"(r) : "f"(lo), "f"(hi));
    return r;
}
__device__ __forceinline__ void upk2(float& lo, float& hi, unsigned long long v) {
    asm("mov.b64 {%0, %1}, %2;" : "=f"(lo), "=f"(hi) : "l"(v));
}
__device__ __forceinline__ unsigned long long ffma2(
    unsigned long long a, unsigned long long b, unsigned long long c) {
    unsigned long long r;
    asm("fma.rn.f32x2 %0, %1, %2, %3;" : "=l"(r) : "l"(a), "l"(b), "l"(c));
    return r;
}
__device__ __forceinline__ unsigned long long fadd2(
    unsigned long long a, unsigned long long b) {
    unsigned long long r;
    asm("add.rn.f32x2 %0, %1, %2;" : "=l"(r) : "l"(a), "l"(b));
    return r;
}

// ---------------------------------------------------------------------------
// Init: collapse conv+relu-MLP assuming b_mlp==0 (exactness flag if not).
//   P[o,k] = sum_{i: Wm_i>0} Wc[o,i,k]*Wm_i ;  N: Wm_i<0.
// ---------------------------------------------------------------------------
__global__ void init_pn_kernel(const float* __restrict__ Wm,
                               const float* __restrict__ bm,
                               const float* __restrict__ Wc)
{
    int tid = threadIdx.x;
    if (tid == 0) {
        int nz = 0;
        for (int i = 0; i < 16; i++) if (bm[i] != 0.0f) nz = 1;
        g_bmnz = nz;
    }
    if (tid < 80) {
        int o = tid / 5, k = tid % 5;
        float p = 0.0f, n = 0.0f;
        for (int i = 0; i < 16; i++) {
            float w = Wm[i];
            float c = Wc[o * 80 + i * 5 + k];
            if (w > 0.0f) p = fmaf(c, w, p);
            else if (w < 0.0f) n = fmaf(c, w, n);
        }
        g_P[tid] = p;
        g_N[tid] = n;
    }
}

// ---------------------------------------------------------------------------
// Pre-pass: one THREAD per (t, b), mapped so a warp covers 32 consecutive t
// for one b (coalesced x loads). y matvec fully packed in f32x2 with pairing
// (j, j+32) == the stored float2. Coalesced writeout via smem stage.
// blockDim = 128 (4 warps); grid = (ceil(2000/128), 256).
// ---------------------------------------------------------------------------
__global__ void __launch_bounds__(128) prepass_kernel(
    const float* __restrict__ x,  const float* __restrict__ Wm,
    const float* __restrict__ bm, const float* __restrict__ Wc,
    const float* __restrict__ bconv, const float* __restrict__ Wx,
    const float* __restrict__ gx, const float* __restrict__ bx,
    const float* __restrict__ bg)
{
    __shared__ float sP[80], sN[80], sbc[16];
    __shared__ float sWm[16], sbm[16];
    __shared__ float sWcT[80 * 16];                 // fallback path only
    __shared__ unsigned long long sWxT2[16][32];    // [o][l] = (Wx[l][o], Wx[l+32][o])
    __shared__ unsigned long long sgx2[32], sbxg2[32];
    __shared__ float2 stage[4][32][33];             // [warp][item][pair] (+pad)

    for (int i = threadIdx.x; i < 80; i += blockDim.x) {
        sP[i] = g_P[i]; sN[i] = g_N[i];
    }
    for (int i = threadIdx.x; i < 16; i += blockDim.x) {
        sbc[i] = bconv[i]; sWm[i] = Wm[i]; sbm[i] = bm[i];
    }
    for (int i = threadIdx.x; i < 80 * 16; i += blockDim.x) {
        int ik = i >> 4, o = i & 15;
        sWcT[i] = Wc[o * 80 + ik];
    }
    for (int i = threadIdx.x; i < 16 * 32; i += blockDim.x) {
        int o = i >> 5, l = i & 31;
        sWxT2[o][l] = pk2(Wx[l * 16 + o], Wx[(l + 32) * 16 + o]);
    }
    for (int i = threadIdx.x; i < 32; i += blockDim.x) {
        sgx2[i]  = pk2(gx[i], gx[i + 32]);
        sbxg2[i] = pk2(bx[i] + bg[i], bx[i + 32] + bg[i + 32]);
    }
    __syncthreads();

    const int bmnz = g_bmnz;
    int lane = threadIdx.x & 31;
    int wrp  = threadIdx.x >> 5;
    int b    = blockIdx.y;
    int tbase = blockIdx.x * 128 + wrp * 32;        // first t of this warp
    int t     = tbase + lane;
    bool valid = (t < T_STEPS);
    int tt = valid ? t : 0;

    // conv + relu-MLP fused
    float xt[16];
    #pragma unroll
    for (int o = 0; o < 16; o++) xt[o] = sbc[o];

    if (!bmnz) {
        // fast path: b_mlp == 0  ->  xt_o += x_k * (x_k>0 ? P[o,k] : N[o,k])
        #pragma unroll
        for (int k = 0; k < KW; k++) {
            float xk = __ldg(&x[b * SEQ + tt * KW + k]);
            const float* PN = (xk > 0.0f) ? sP : sN;
            #pragma unroll
            for (int o = 0; o < 16; o++)
                xt[o] = fmaf(xk, PN[o * 5 + k], xt[o]);
        }
    } else {
        // exact general path
        #pragma unroll
        for (int k = 0; k < KW; k++) {
            float xk = __ldg(&x[b * SEQ + tt * KW + k]);
            #pragma unroll
            for (int i = 0; i < 16; i++) {
                float f = fmaxf(fmaf(xk, sWm[i], sbm[i]), 0.0f);
                const float4* wr = (const float4*)&sWcT[(i * KW + k) * 16];
                #pragma unroll
                for (int o4 = 0; o4 < 4; o4++) {
                    float4 w = wr[o4];
                    xt[o4 * 4 + 0] = fmaf(w.x, f, xt[o4 * 4 + 0]);
                    xt[o4 * 4 + 1] = fmaf(w.y, f, xt[o4 * 4 + 1]);
                    xt[o4 * 4 + 2] = fmaf(w.z, f, xt[o4 * 4 + 2]);
                    xt[o4 * 4 + 3] = fmaf(w.w, f, xt[o4 * 4 + 3]);
                }
            }
        }
    }
    #pragma unroll
    for (int o = 0; o < 16; o++) xt[o] = sigf(xt[o]);

    // y = xt @ Wx^T, packed: y2[l] = (y[l], y[l+32])
    unsigned long long y2[32];
    #pragma unroll
    for (int l = 0; l < 32; l++) y2[l] = 0ull;
    #pragma unroll
    for (int o = 0; o < 16; o++) {
        unsigned long long x2 = pk2(xt[o], xt[o]);
        #pragma unroll
        for (int l = 0; l < 32; l++)
            y2[l] = ffma2(sWxT2[o][l], x2, y2[l]);
    }

    // LN over the 64 values (packed accumulation)
    unsigned long long s2 = 0ull, q2 = 0ull;
    #pragma unroll
    for (int l = 0; l < 32; l++) {
        s2 = fadd2(s2, y2[l]);
        q2 = ffma2(y2[l], y2[l], q2);
    }
    float sa, sb, qa, qb;
    upk2(sa, sb, s2); upk2(qa, qb, q2);
    float s = sa + sb, q = qa + qb;
    float mean = s * (1.0f / 64.0f);
    float var  = fmaf(-mean, mean, q * (1.0f / 64.0f));
    float r    = rsqrtf(var + 1e-5f);

    unsigned long long r2  = pk2(r, r);
    unsigned long long nmr = pk2(-mean * r, -mean * r);

    #pragma unroll
    for (int l = 0; l < 32; l++) {
        unsigned long long tnorm = ffma2(y2[l], r2, nmr);      // (y-mean)*r
        unsigned long long a2    = ffma2(tnorm, sgx2[l], sbxg2[l]);
        float a0, a1; upk2(a0, a1, a2);
        stage[wrp][lane][l] = make_float2(a0, a1);
    }
    __syncwarp();

    // coalesced writeout: item k of this warp -> 256B contiguous chunk
    float2* gax2 = (float2*)g_ax;
    #pragma unroll 4
    for (int k = 0; k < 32; k++) {
        int tk = tbase + k;
        if (tk < T_STEPS)
            gax2[((size_t)tk * 256 + b) * 32 + lane] = stage[wrp][k][lane];
    }
}

// ---------------------------------------------------------------------------
// Sequential LSTM scan. ONE warp = ONE batch row.
//   lane l: gate rows ja=l (i|f), jb=l+32 (g|o); c/h on upper 16 lanes.
//   Reductions = fan-in-4 shuffle trees (3 indep shfl_xor per level).
// ---------------------------------------------------------------------------
__global__ void __launch_bounds__(32, 1) lstm_seq_kernel(
    const float* __restrict__ Wh,   const float* __restrict__ gh,
    const float* __restrict__ bh,   const float* __restrict__ gc,
    const float* __restrict__ bc,   const float* __restrict__ Wcls,
    const float* __restrict__ bcls, const float* __restrict__ h0,
    const float* __restrict__ c0,   float* __restrict__ out)
{
    const unsigned ALL = 0xffffffffu;
    int lane  = threadIdx.x;
    int m     = lane & 15;
    bool upper = lane >= 16;
    int row   = blockIdx.x;

    float wa[16], wb[16];
    #pragma unroll
    for (int i = 0; i < 16; i++) {
        wa[i] = Wh[lane * 16 + i];
        wb[i] = Wh[(lane + 32) * 16 + i];
    }
    float gha = gh[lane], ghb = gh[lane + 32];
    float bha = bh[lane], bhb = bh[lane + 32];
    float gcm = gc[m],    bcm = bc[m];

    float h = h0[row * 16 + m];
    float c = c0[row * 16 + m];

    const float2* ax = (const float2*)g_ax;
    int base = row * 32 + lane;
    const int stride = BATCH * 32;
    float2 p0 = ax[base];
    float2 p1 = ax[base + stride];

    #pragma unroll 2
    for (int t = 0; t < T_STEPS; t++) {
        float2 cur = p0;
        p0 = p1;
        if (t + 2 < T_STEPS) p1 = ax[base + (t + 2) * stride];

        // matvec: broadcast h[i] from lanes 16..31, 4 FMA chains
        float ya0, ya1, yb0, yb1;
        {
            float h0v = __shfl_sync(ALL, h, 16);
            float h1v = __shfl_sync(ALL, h, 17);
            ya0 = wa[0] * h0v; ya1 = wa[1] * h1v;
            yb0 = wb[0] * h0v; yb1 = wb[1] * h1v;
        }
        #pragma unroll
        for (int i = 2; i < 16; i += 2) {
            float hvA = __shfl_sync(ALL, h, 16 + i);
            float hvB = __shfl_sync(ALL, h, 17 + i);
            ya0 = fmaf(wa[i],     hvA, ya0);
            ya1 = fmaf(wa[i + 1], hvB, ya1);
            yb0 = fmaf(wb[i],     hvA, yb0);
            yb1 = fmaf(wb[i + 1], hvB, yb1);
        }
        float ya = ya0 + ya1;
        float yb = yb0 + yb1;

        // LN64: fan-in-4 reduction over 32 lanes, 3 levels
        float s = ya + yb;
        float q = fmaf(ya, ya, yb * yb);
        {
            float sA = __shfl_xor_sync(ALL, s, 1);
            float sB = __shfl_xor_sync(ALL, s, 2);
            float sC = __shfl_xor_sync(ALL, s, 3);
            float qA = __shfl_xor_sync(ALL, q, 1);
            float qB = __shfl_xor_sync(ALL, q, 2);
            float qC = __shfl_xor_sync(ALL, q, 3);
            s = (s + sA) + (sB + sC);
            q = (q + qA) + (qB + qC);
        }
        {
            float sA = __shfl_xor_sync(ALL, s, 4);
            float sB = __shfl_xor_sync(ALL, s, 8);
            float sC = __shfl_xor_sync(ALL, s, 12);
            float qA = __shfl_xor_sync(ALL, q, 4);
            float qB = __shfl_xor_sync(ALL, q, 8);
            float qC = __shfl_xor_sync(ALL, q, 12);
            s = (s + sA) + (sB + sC);
            q = (q + qA) + (qB + qC);
        }
        s += __shfl_xor_sync(ALL, s, 16);
        q += __shfl_xor_sync(ALL, q, 16);

        float mean = s * (1.0f / 64.0f);
        float var  = fmaf(-mean, mean, q * (1.0f / 64.0f));
        float r    = rsqrtf(var + 1e-5f);

        float ga = fmaf((ya - mean) * r, gha, bha) + cur.x;  // i | f
        float gb = fmaf((yb - mean) * r, ghb, bhb) + cur.y;  // g | o

        float u1 = sigf(ga);                                  // sig(i) | sig(f)
        float u2 = sigf(upper ? gb : (2.0f * gb));            // sig(o) | sig(2g)
        float Aval = u1 * fmaf(2.0f, u2, -1.0f);              // lower: sig(i)*tanh(g)
        float A = __shfl_xor_sync(ALL, Aval, 16);

        float cnew = fmaf(u1, c, A);
        c = upper ? cnew : 0.0f;

        // LN16: fan-in-4 over the 16 upper lanes, 2 levels
        float sc = c, qc = c * c;
        {
            float sA = __shfl_xor_sync(ALL, sc, 1);
            float sB = __shfl_xor_sync(ALL, sc, 2);
            float sC = __shfl_xor_sync(ALL, sc, 3);
            float qA = __shfl_xor_sync(ALL, qc, 1);
            float qB = __shfl_xor_sync(ALL, qc, 2);
            float qC = __shfl_xor_sync(ALL, qc, 3);
            sc = (sc + sA) + (sB + sC);
            qc = (qc + qA) + (qB + qC);
        }
        {
            float sA = __shfl_xor_sync(ALL, sc, 4);
            float sB = __shfl_xor_sync(ALL, sc, 8);
            float sC = __shfl_xor_sync(ALL, sc, 12);
            float qA = __shfl_xor_sync(ALL, qc, 4);
            float qB = __shfl_xor_sync(ALL, qc, 8);
            float qC = __shfl_xor_sync(ALL, qc, 12);
            sc = (sc + sA) + (sB + sC);
            qc = (qc + qA) + (qB + qC);
        }
        float mc = sc * (1.0f / 16.0f);
        float vc = fmaf(-mc, mc, qc * (1.0f / 16.0f));
        float rc = rsqrtf(vc + 1e-5f);
        float cn = fmaf((c - mc) * rc, gcm, bcm);
        float th = fmaf(2.0f, sigf(2.0f * cn), -1.0f);        // tanh(cn)
        h = u2 * th;                                          // upper valid
    }

    // classifier
    float v = upper ? h * Wcls[m] : 0.0f;
    #pragma unroll
    for (int d = 16; d >= 1; d >>= 1)
        v += __shfl_xor_sync(ALL, v, d);
    if (lane == 0)
        out[row] = sigf(v + bcls[0]);
}

// ---------------------------------------------------------------------------
extern "C" void kernel_launch(void* const* d_in, const int* in_sizes, int n_in,
                              void* d_out, int out_size)
{
    const float* x     = (const float*)d_in[0];
    const float* Wm    = (const float*)d_in[1];
    const float* bm    = (const float*)d_in[2];
    const float* Wc    = (const float*)d_in[3];
    const float* bconv = (const float*)d_in[4];
    const float* Wx    = (const float*)d_in[5];
    const float* Wh    = (const float*)d_in[6];
    const float* bg    = (const float*)d_in[7];
    const float* gx    = (const float*)d_in[8];
    const float* bx    = (const float*)d_in[9];
    const float* gh    = (const float*)d_in[10];
    const float* bh    = (const float*)d_in[11];
    const float* gc    = (const float*)d_in[12];
    const float* bc    = (const float*)d_in[13];
    const float* Wcls  = (const float*)d_in[14];
    const float* bcls  = (const float*)d_in[15];
    const float* h0    = (const float*)d_in[16];
    const float* c0    = (const float*)d_in[17];
    float* out = (float*)d_out;

    init_pn_kernel<<<1, 128>>>(Wm, bm, Wc);
    dim3 pgrid((T_STEPS + 127) / 128, BATCH);
    prepass_kernel<<<pgrid, 128>>>(x, Wm, bm, Wc, bconv, Wx, gx, bx, bg);
    lstm_seq_kernel<<<BATCH, 32>>>(Wh, gh, bh, gc, bc, Wcls, bcls, h0, c0, out);
}

// round 5
// speedup vs baseline: 1.2149x; 1.2149x over previous
#include <cuda_runtime.h>

#define T_STEPS 2000
#define BATCH   256
#define SEQ     10000
#define KW      5

// Gate pre-activations a_x[t][b][j] = LN64(xt@Wx^T)[j]*gx[j] + bx[j] + b_gates[j],
// stored so float2 at (t*256+b)*32 + l = { a[j=l], a[j=l+32] }.
__device__ float g_ax[(size_t)T_STEPS * BATCH * 64];
// Precomputed conv collapse (valid when b_mlp == 0): P/N[o*5+k]
__device__ float g_P[80];
__device__ float g_N[80];
__device__ int   g_bmnz;
// Column-centered weights: W[j,i] - (1/64) sum_j' W[j',i].
// LN(y) mean folds into weights: y' = WC.h  ==  y - mean(y), so only var
// needs a reduction (var = sum(y'^2)/64).
__device__ float g_WhC[64 * 16];
__device__ float g_WxC[64 * 16];

__device__ __forceinline__ float sigf(float x) {
    return __fdividef(1.0f, 1.0f + __expf(-x));
}

// ---- f32x2 packed helpers (sm_103a) --------------------------------------
__device__ __forceinline__ unsigned long long pk2(float lo, float hi) {
    unsigned long long r;
    asm("mov.b64 %0, {%1, %2};" : "=l"(r) : "f"(lo), "f"(hi));
    return r;
}
__device__ __forceinline__ void upk2(float& lo, float& hi, unsigned long long v) {
    asm("mov.b64 {%0, %1}, %2;" : "=f"(lo), "=f"(hi) : "l"(v));
}
__device__ __forceinline__ unsigned long long ffma2(
    unsigned long long a, unsigned long long b, unsigned long long c) {
    unsigned long long r;
    asm("fma.rn.f32x2 %0, %1, %2, %3;" : "=l"(r) : "l"(a), "l"(b), "l"(c));
    return r;
}
__device__ __forceinline__ unsigned long long fadd2(
    unsigned long long a, unsigned long long b) {
    unsigned long long r;
    asm("add.rn.f32x2 %0, %1, %2;" : "=l"(r) : "l"(a), "l"(b));
    return r;
}
__device__ __forceinline__ unsigned long long fmul2(
    unsigned long long a, unsigned long long b) {
    unsigned long long r;
    asm("mul.rn.f32x2 %0, %1, %2;" : "=l"(r) : "l"(a), "l"(b));
    return r;
}

// ---------------------------------------------------------------------------
// Init: P/N conv collapse + column-centered WhC / WxC.
// ---------------------------------------------------------------------------
__global__ void init_kernel(const float* __restrict__ Wm,
                            const float* __restrict__ bm,
                            const float* __restrict__ Wc,
                            const float* __restrict__ Wh,
                            const float* __restrict__ Wx)
{
    __shared__ float cmh[16], cmx[16];
    int tid = threadIdx.x;
    if (tid == 0) {
        int nz = 0;
        for (int i = 0; i < 16; i++) if (bm[i] != 0.0f) nz = 1;
        g_bmnz = nz;
    }
    if (tid < 16) {
        float sh = 0.0f, sx = 0.0f;
        for (int j = 0; j < 64; j++) {
            sh += Wh[j * 16 + tid];
            sx += Wx[j * 16 + tid];
        }
        cmh[tid] = sh * (1.0f / 64.0f);
        cmx[tid] = sx * (1.0f / 64.0f);
    }
    if (tid < 80) {
        int o = tid / 5, k = tid % 5;
        float p = 0.0f, n = 0.0f;
        for (int i = 0; i < 16; i++) {
            float w = Wm[i];
            float c = Wc[o * 80 + i * 5 + k];
            if (w > 0.0f) p = fmaf(c, w, p);
            else if (w < 0.0f) n = fmaf(c, w, n);
        }
        g_P[tid] = p;
        g_N[tid] = n;
    }
    __syncthreads();
    for (int idx = tid; idx < 1024; idx += blockDim.x) {
        int i = idx & 15;
        g_WhC[idx] = Wh[idx] - cmh[i];
        g_WxC[idx] = Wx[idx] - cmx[i];
    }
}

// ---------------------------------------------------------------------------
// Pre-pass: one THREAD per (t, b); warp covers 32 consecutive t of one b
// (coalesced x loads). Centered WxC -> no mean reduction. Packed f32x2.
// ---------------------------------------------------------------------------
__global__ void __launch_bounds__(128) prepass_kernel(
    const float* __restrict__ x,  const float* __restrict__ Wm,
    const float* __restrict__ bm, const float* __restrict__ Wc,
    const float* __restrict__ bconv,
    const float* __restrict__ gx, const float* __restrict__ bx,
    const float* __restrict__ bg)
{
    __shared__ float sP[80], sN[80], sbc[16];
    __shared__ float sWm[16], sbm[16];
    __shared__ float sWcT[80 * 16];                 // fallback path only
    __shared__ unsigned long long sWxT2[16][32];    // [o][l] = (WxC[l][o], WxC[l+32][o])
    __shared__ unsigned long long sgx2[32], sbxg2[32];
    __shared__ float2 stage[4][32][33];             // [warp][item][pair] (+pad)

    const float* Wc_ = Wc;
    for (int i = threadIdx.x; i < 80; i += blockDim.x) {
        sP[i] = g_P[i]; sN[i] = g_N[i];
    }
    for (int i = threadIdx.x; i < 16; i += blockDim.x) {
        sbc[i] = bconv[i]; sWm[i] = Wm[i]; sbm[i] = bm[i];
    }
    for (int i = threadIdx.x; i < 80 * 16; i += blockDim.x) {
        int ik = i >> 4, o = i & 15;
        sWcT[i] = Wc_[o * 80 + ik];
    }
    for (int i = threadIdx.x; i < 16 * 32; i += blockDim.x) {
        int o = i >> 5, l = i & 31;
        sWxT2[o][l] = pk2(g_WxC[l * 16 + o], g_WxC[(l + 32) * 16 + o]);
    }
    for (int i = threadIdx.x; i < 32; i += blockDim.x) {
        sgx2[i]  = pk2(gx[i], gx[i + 32]);
        sbxg2[i] = pk2(bx[i] + bg[i], bx[i + 32] + bg[i + 32]);
    }
    __syncthreads();

    const int bmnz = g_bmnz;
    int lane = threadIdx.x & 31;
    int wrp  = threadIdx.x >> 5;
    int b    = blockIdx.y;
    int tbase = blockIdx.x * 128 + wrp * 32;
    int t     = tbase + lane;
    int tt = (t < T_STEPS) ? t : 0;

    // conv + relu-MLP fused
    float xt[16];
    #pragma unroll
    for (int o = 0; o < 16; o++) xt[o] = sbc[o];

    if (!bmnz) {
        #pragma unroll
        for (int k = 0; k < KW; k++) {
            float xk = __ldg(&x[b * SEQ + tt * KW + k]);
            const float* PN = (xk > 0.0f) ? sP : sN;
            #pragma unroll
            for (int o = 0; o < 16; o++)
                xt[o] = fmaf(xk, PN[o * 5 + k], xt[o]);
        }
    } else {
        #pragma unroll
        for (int k = 0; k < KW; k++) {
            float xk = __ldg(&x[b * SEQ + tt * KW + k]);
            #pragma unroll
            for (int i = 0; i < 16; i++) {
                float f = fmaxf(fmaf(xk, sWm[i], sbm[i]), 0.0f);
                const float4* wr = (const float4*)&sWcT[(i * KW + k) * 16];
                #pragma unroll
                for (int o4 = 0; o4 < 4; o4++) {
                    float4 w = wr[o4];
                    xt[o4 * 4 + 0] = fmaf(w.x, f, xt[o4 * 4 + 0]);
                    xt[o4 * 4 + 1] = fmaf(w.y, f, xt[o4 * 4 + 1]);
                    xt[o4 * 4 + 2] = fmaf(w.z, f, xt[o4 * 4 + 2]);
                    xt[o4 * 4 + 3] = fmaf(w.w, f, xt[o4 * 4 + 3]);
                }
            }
        }
    }
    #pragma unroll
    for (int o = 0; o < 16; o++) xt[o] = sigf(xt[o]);

    // y' = xt @ WxC^T, packed: y2[l] = (y'[l], y'[l+32]); mean(y')==0 by construction
    unsigned long long y2[32];
    #pragma unroll
    for (int l = 0; l < 32; l++) y2[l] = 0ull;
    #pragma unroll
    for (int o = 0; o < 16; o++) {
        unsigned long long x2 = pk2(xt[o], xt[o]);
        #pragma unroll
        for (int l = 0; l < 32; l++)
            y2[l] = ffma2(sWxT2[o][l], x2, y2[l]);
    }

    // var = sum(y'^2)/64
    unsigned long long q2a = 0ull, q2b = 0ull;
    #pragma unroll
    for (int l = 0; l < 32; l += 2) {
        q2a = ffma2(y2[l],     y2[l],     q2a);
        q2b = ffma2(y2[l + 1], y2[l + 1], q2b);
    }
    float qa, qb, qc, qd;
    upk2(qa, qb, q2a); upk2(qc, qd, q2b);
    float q = (qa + qb) + (qc + qd);
    float r = rsqrtf(q * (1.0f / 64.0f) + 1e-5f);

    unsigned long long r2 = pk2(r, r);
    #pragma unroll
    for (int l = 0; l < 32; l++) {
        unsigned long long tnorm = fmul2(y2[l], r2);
        unsigned long long a2    = ffma2(tnorm, sgx2[l], sbxg2[l]);
        float a0, a1; upk2(a0, a1, a2);
        stage[wrp][lane][l] = make_float2(a0, a1);
    }
    __syncwarp();

    // coalesced writeout
    float2* gax2 = (float2*)g_ax;
    #pragma unroll 4
    for (int k = 0; k < 32; k++) {
        int tk = tbase + k;
        if (tk < T_STEPS)
            gax2[((size_t)tk * 256 + b) * 32 + lane] = stage[wrp][k][lane];
    }
}

// ---------------------------------------------------------------------------
// Sequential LSTM scan. ONE warp = ONE batch row.
//   lane l: gate rows ja=l (i|f), jb=l+32 (g|o); c/h state on upper 16 lanes.
//   LN64 mean folded into centered WhC (no reduction); var + LN16 stats via
//   smem gather-reduction (STS -> syncwarp -> LDS.128 broadcast -> local
//   packed sum). Only ONE shuffle per step (the Aval/sig(f) exchange).
// ---------------------------------------------------------------------------
__global__ void __launch_bounds__(32) lstm_seq_kernel(
    const float* __restrict__ gh,   const float* __restrict__ bh,
    const float* __restrict__ gc,   const float* __restrict__ bc,
    const float* __restrict__ Wcls, const float* __restrict__ bcls,
    const float* __restrict__ h0,   const float* __restrict__ c0,
    float* __restrict__ out)
{
    const unsigned ALL = 0xffffffffu;
    int lane  = threadIdx.x;
    int m     = lane & 15;
    bool upper = lane >= 16;
    int row   = blockIdx.x;

    __shared__ float sh[16];      // h broadcast
    __shared__ float sqp[32];     // per-lane q partials
    __shared__ float sc16[16];    // c values

    float wa[16], wb[16];
    #pragma unroll
    for (int i = 0; i < 16; i++) {
        wa[i] = g_WhC[lane * 16 + i];
        wb[i] = g_WhC[(lane + 32) * 16 + i];
    }
    float gha = gh[lane], ghb = gh[lane + 32];
    float bha = bh[lane], bhb = bh[lane + 32];
    float gcm = gc[m],    bcm = bc[m];

    float h = h0[row * 16 + m];
    float c = c0[row * 16 + m];
    if (upper) sh[m] = h;
    __syncwarp();

    const float2* ax = (const float2*)g_ax;
    int base = row * 32 + lane;
    const int stride = BATCH * 32;
    float2 p0 = ax[base];
    float2 p1 = ax[base + stride];

    for (int t = 0; t < T_STEPS; t++) {
        // --- h broadcast (conflict-free LDS.128 broadcast reads) ---
        const float4* hb = (const float4*)sh;
        float4 hv0 = hb[0], hv1 = hb[1], hv2 = hb[2], hv3 = hb[3];

        float2 cur = p0;
        p0 = p1;
        if (t + 2 < T_STEPS) p1 = ax[base + (t + 2) * stride];

        // --- centered matvec: y' rows ja, jb (4 independent FMA chains) ---
        float ya0, ya1, yb0, yb1;
        ya0 = wa[0] * hv0.x; ya1 = wa[1] * hv0.y;
        yb0 = wb[0] * hv0.x; yb1 = wb[1] * hv0.y;
        ya0 = fmaf(wa[2],  hv0.z, ya0); ya1 = fmaf(wa[3],  hv0.w, ya1);
        yb0 = fmaf(wb[2],  hv0.z, yb0); yb1 = fmaf(wb[3],  hv0.w, yb1);
        ya0 = fmaf(wa[4],  hv1.x, ya0); ya1 = fmaf(wa[5],  hv1.y, ya1);
        yb0 = fmaf(wb[4],  hv1.x, yb0); yb1 = fmaf(wb[5],  hv1.y, yb1);
        ya0 = fmaf(wa[6],  hv1.z, ya0); ya1 = fmaf(wa[7],  hv1.w, ya1);
        yb0 = fmaf(wb[6],  hv1.z, yb0); yb1 = fmaf(wb[7],  hv1.w, yb1);
        ya0 = fmaf(wa[8],  hv2.x, ya0); ya1 = fmaf(wa[9],  hv2.y, ya1);
        yb0 = fmaf(wb[8],  hv2.x, yb0); yb1 = fmaf(wb[9],  hv2.y, yb1);
        ya0 = fmaf(wa[10], hv2.z, ya0); ya1 = fmaf(wa[11], hv2.w, ya1);
        yb0 = fmaf(wb[10], hv2.z, yb0); yb1 = fmaf(wb[11], hv2.w, yb1);
        ya0 = fmaf(wa[12], hv3.x, ya0); ya1 = fmaf(wa[13], hv3.y, ya1);
        yb0 = fmaf(wb[12], hv3.x, yb0); yb1 = fmaf(wb[13], hv3.y, yb1);
        ya0 = fmaf(wa[14], hv3.z, ya0); ya1 = fmaf(wa[15], hv3.w, ya1);
        yb0 = fmaf(wb[14], hv3.z, yb0); yb1 = fmaf(wb[15], hv3.w, yb1);
        float ya = ya0 + ya1;
        float yb = yb0 + yb1;

        // --- var reduction via smem gather (mean == 0 by construction) ---
        sqp[lane] = fmaf(ya, ya, yb * yb);
        __syncwarp();
        const unsigned long long* qv = (const unsigned long long*)sqp;
        unsigned long long t0 = fadd2(qv[0],  qv[1]);
        unsigned long long t1 = fadd2(qv[2],  qv[3]);
        unsigned long long t2 = fadd2(qv[4],  qv[5]);
        unsigned long long t3 = fadd2(qv[6],  qv[7]);
        unsigned long long t4 = fadd2(qv[8],  qv[9]);
        unsigned long long t5 = fadd2(qv[10], qv[11]);
        unsigned long long t6 = fadd2(qv[12], qv[13]);
        unsigned long long t7 = fadd2(qv[14], qv[15]);
        t0 = fadd2(t0, t1); t2 = fadd2(t2, t3);
        t4 = fadd2(t4, t5); t6 = fadd2(t6, t7);
        t0 = fadd2(t0, t2); t4 = fadd2(t4, t6);
        t0 = fadd2(t0, t4);
        float qlo, qhi; upk2(qlo, qhi, t0);
        float q = qlo + qhi;
        float r = rsqrtf(q * (1.0f / 64.0f) + 1e-5f);

        float ga = fmaf(ya * r, gha, bha) + cur.x;   // i | f
        float gb = fmaf(yb * r, ghb, bhb) + cur.y;   // g | o

        float u1 = sigf(ga);                          // sig(i) | sig(f)
        float u2 = sigf(upper ? gb : (2.0f * gb));    // sig(o) | sig(2g)
        float Aval = u1 * fmaf(2.0f, u2, -1.0f);      // lower: sig(i)*tanh(g)
        float A = __shfl_xor_sync(ALL, Aval, 16);

        c = fmaf(u1, c, A);                           // valid on upper lanes
        if (upper) sc16[m] = c;
        __syncwarp();

        // --- LN16 stats via smem gather ---
        const unsigned long long* cv = (const unsigned long long*)sc16;
        unsigned long long s0 = fadd2(cv[0], cv[1]);
        unsigned long long s1 = fadd2(cv[2], cv[3]);
        unsigned long long s2 = fadd2(cv[4], cv[5]);
        unsigned long long s3 = fadd2(cv[6], cv[7]);
        unsigned long long z0 = ffma2(cv[0], cv[0], 0ull);
        unsigned long long z1 = ffma2(cv[1], cv[1], 0ull);
        unsigned long long z2 = ffma2(cv[2], cv[2], 0ull);
        unsigned long long z3 = ffma2(cv[3], cv[3], 0ull);
        z0 = ffma2(cv[4], cv[4], z0);
        z1 = ffma2(cv[5], cv[5], z1);
        z2 = ffma2(cv[6], cv[6], z2);
        z3 = ffma2(cv[7], cv[7], z3);
        s0 = fadd2(s0, s1); s2 = fadd2(s2, s3);
        z0 = fadd2(z0, z1); z2 = fadd2(z2, z3);
        s0 = fadd2(s0, s2); z0 = fadd2(z0, z2);
        float slo, shi, zlo, zhi;
        upk2(slo, shi, s0); upk2(zlo, zhi, z0);
        float sc = slo + shi, qc = zlo + zhi;

        float mc = sc * (1.0f / 16.0f);
        float vc = fmaf(-mc, mc, qc * (1.0f / 16.0f));
        float rc = rsqrtf(vc + 1e-5f);
        float cn = fmaf((c - mc) * rc, gcm, bcm);
        float th = fmaf(2.0f, sigf(2.0f * cn), -1.0f); // tanh(cn)
        h = u2 * th;                                   // valid on upper lanes
        if (upper) sh[m] = h;
        __syncwarp();
    }

    // classifier: sigmoid(h . W_cls + b_cls)  (h valid on upper lanes)
    float v = upper ? h * Wcls[m] : 0.0f;
    #pragma unroll
    for (int d = 16; d >= 1; d >>= 1)
        v += __shfl_xor_sync(ALL, v, d);
    if (lane == 0)
        out[row] = sigf(v + bcls[0]);
}

// ---------------------------------------------------------------------------
extern "C" void kernel_launch(void* const* d_in, const int* in_sizes, int n_in,
                              void* d_out, int out_size)
{
    const float* x     = (const float*)d_in[0];
    const float* Wm    = (const float*)d_in[1];
    const float* bm    = (const float*)d_in[2];
    const float* Wc    = (const float*)d_in[3];
    const float* bconv = (const float*)d_in[4];
    const float* Wx    = (const float*)d_in[5];
    const float* Wh    = (const float*)d_in[6];
    const float* bg    = (const float*)d_in[7];
    const float* gx    = (const float*)d_in[8];
    const float* bx    = (const float*)d_in[9];
    const float* gh    = (const float*)d_in[10];
    const float* bh    = (const float*)d_in[11];
    const float* gc    = (const float*)d_in[12];
    const float* bc    = (const float*)d_in[13];
    const float* Wcls  = (const float*)d_in[14];
    const float* bcls  = (const float*)d_in[15];
    const float* h0    = (const float*)d_in[16];
    const float* c0    = (const float*)d_in[17];
    float* out = (float*)d_out;

    init_kernel<<<1, 128>>>(Wm, bm, Wc, Wh, Wx);
    dim3 pgrid((T_STEPS + 127) / 128, BATCH);
    prepass_kernel<<<pgrid, 128>>>(x, Wm, bm, Wc, bconv, gx, bx, bg);
    lstm_seq_kernel<<<BATCH, 32>>>(gh, bh, gc, bc, Wcls, bcls, h0, c0, out);
}